// round 7
// baseline (speedup 1.0000x reference)
#include <cuda_runtime.h>

typedef unsigned long long ull;
typedef unsigned int u32;

#define NROWS   16384
#define DIMP    1024
#define NCLS    10
#define IMG     784
#define QSTRIDE 22                    // ull per d-quad group: 20 data + 2 pad (176 B)

#define REF_BYTES   45056             // 256 groups * 176 B
#define STAGE_BYTES 16384             // 16 rows * 512 B * 2 (re,im)
#define NSTAGE      3
#define STAGE_OFF   REF_BYTES
#define MBAR_OFF    (STAGE_OFF + NSTAGE * STAGE_BYTES)   // 94208; full[3] then empty[3]
#define SMEM_TOTAL  (MBAR_OFF + 64)

// Packed reference pairs (prologue output), dense layout:
// g_refp[(d>>2)*20 + p*4 + (d&3)] = ( ref[2p][d], ref[2p+1][d] )
__device__ ull g_refp[256 * 20];

// ---------- f32x2 helpers ----------
__device__ __forceinline__ ull pack2(float lo, float hi) {
    ull r;
    asm("mov.b64 %0, {%1, %2};" : "=l"(r) : "f"(lo), "f"(hi));
    return r;
}
__device__ __forceinline__ void unpack2(ull v, float& lo, float& hi) {
    asm("mov.b64 {%0, %1}, %2;" : "=f"(lo), "=f"(hi) : "l"(v));
}
__device__ __forceinline__ void fma2(ull& acc, ull a, ull b) {
    asm("fma.rn.f32x2 %0, %1, %2, %0;" : "+l"(acc) : "l"(a), "l"(b));
}
__device__ __forceinline__ void add2(ull& acc, ull a) {
    asm("add.rn.f32x2 %0, %1, %0;" : "+l"(acc) : "l"(a));
}

// ---------- TMA / mbarrier helpers ----------
__device__ __forceinline__ u32 smem_u32(const void* p) {
    u32 a;
    asm("{ .reg .u64 t; cvta.to.shared.u64 t, %1; cvt.u32.u64 %0, t; }" : "=r"(a) : "l"(p));
    return a;
}
__device__ __forceinline__ void mbar_init(u32 mbar, u32 cnt) {
    asm volatile("mbarrier.init.shared.b64 [%0], %1;" :: "r"(mbar), "r"(cnt) : "memory");
}
__device__ __forceinline__ void mbar_expect_tx(u32 mbar, u32 bytes) {
    asm volatile("mbarrier.arrive.expect_tx.shared.b64 _, [%0], %1;" :: "r"(mbar), "r"(bytes) : "memory");
}
__device__ __forceinline__ void mbar_arrive(u32 mbar) {
    asm volatile("mbarrier.arrive.shared.b64 _, [%0];" :: "r"(mbar) : "memory");
}
__device__ __forceinline__ void mbar_wait(u32 mbar, u32 phase) {
    asm volatile(
        "{\n\t.reg .pred P;\n\t"
        "W%=:\n\t"
        "mbarrier.try_wait.parity.acquire.cta.shared::cta.b64 P, [%0], %1, 0x989680;\n\t"
        "@!P bra W%=;\n\t"
        "}" :: "r"(mbar), "r"(phase) : "memory");
}
__device__ __forceinline__ void bulk_cp(u32 dst, const void* src, u32 bytes, u32 mbar) {
    asm volatile(
        "cp.async.bulk.shared::cta.global.mbarrier::complete_tx::bytes [%0], [%1], %2, [%3];"
        :: "r"(dst), "l"(src), "r"(bytes), "r"(mbar) : "memory");
}

// ---------- prologue: block p normalizes classes 2p, 2p+1, writes packed pairs ----------
__global__ void ref_pack_kernel(const float* __restrict__ canon) {
    __shared__ float v0[DIMP], v1[DIMP];
    __shared__ float wred[16];
    __shared__ float invs[2];
    const int p = blockIdx.x, t = threadIdx.x;
    const float* c0 = canon + (2 * p) * IMG;
    const float* c1 = canon + (2 * p + 1) * IMG;
    float s0 = 0.f, s1 = 0.f;
    for (int i = t; i < DIMP; i += 256) {
        float a = (i < IMG) ? c0[i] : 0.f;
        float b = (i < IMG) ? c1[i] : 0.f;
        v0[i] = a; v1[i] = b;
        s0 += a * a; s1 += b * b;
    }
    #pragma unroll
    for (int o = 16; o; o >>= 1) {
        s0 += __shfl_xor_sync(0xFFFFFFFFu, s0, o);
        s1 += __shfl_xor_sync(0xFFFFFFFFu, s1, o);
    }
    if ((t & 31) == 0) { wred[t >> 5] = s0; wred[8 + (t >> 5)] = s1; }
    __syncthreads();
    if (t == 0) {
        float a = 0.f, b = 0.f;
        #pragma unroll
        for (int i = 0; i < 8; i++) { a += wred[i]; b += wred[8 + i]; }
        invs[0] = 1.0f / sqrtf(a);
        invs[1] = 1.0f / sqrtf(b);
    }
    __syncthreads();
    const float i0 = invs[0], i1 = invs[1];
    for (int d = t; d < DIMP; d += 256)
        g_refp[(d >> 2) * 20 + p * 4 + (d & 3)] = pack2(v0[d] * i0, v1[d] * i1);
}

// ---------- main kernel ----------
// 256 threads = 8 warps, 2 rows/warp -> 16 rows/block, grid = 1024.
// z streamed via 3-stage cp.async.bulk pipeline; NO block barriers in the loop:
//  - consumers wait full[s], latch z into regs, warp-elect arrive empty[s]
//  - warp 0 lanes refill stage s after empty[s] phase completes (8 arrivals)
__global__ __launch_bounds__(256, 2) void swap_test_kernel(
    const float* __restrict__ zre, const float* __restrict__ zim,
    float* __restrict__ out) {

    extern __shared__ __align__(16) char smem[];
    const u32 sbase = smem_u32(smem);
    const int tid  = threadIdx.x;
    const int lane = tid & 31;
    const int w    = tid >> 5;
    const int rowBase0 = blockIdx.x * 16;
    const u32 FULL  = sbase + MBAR_OFF;        // full[s]  = FULL  + s*8
    const u32 EMPTY = sbase + MBAR_OFF + 24;   // empty[s] = EMPTY + s*8

    // stage packed ref into smem (176 B groups: 20 data ull + 2 pad)
    {
        ull* s = (ull*)smem;
        for (int i = tid; i < 5120; i += 256) {
            const int q = i / 20;
            const int r = i - q * 20;
            s[q * QSTRIDE + r] = g_refp[i];
        }
    }
    if (tid == 0) {
        #pragma unroll
        for (int s = 0; s < NSTAGE; s++) {
            mbar_init(FULL  + s * 8, 1);   // producer expect_tx
            mbar_init(EMPTY + s * 8, 8);   // one arrive per warp
        }
    }
    __syncthreads();

    // producers: warp 0 lanes prime stages 0..2 (lane -> one 512 B row-chunk)
    const int parr = lane >> 4, prow = lane & 15;
    const float* pbase = (parr ? zim : zre) + (size_t)(rowBase0 + prow) * DIMP;
    if (tid < 32) {
        #pragma unroll
        for (int kk = 0; kk < NSTAGE; kk++) {
            if (lane == 0) mbar_expect_tx(FULL + kk * 8, STAGE_BYTES);
            __syncwarp();
            bulk_cp(sbase + STAGE_OFF + kk * STAGE_BYTES + parr * 8192 + prow * 512,
                    pbase + kk * 128, 512, FULL + kk * 8);
        }
    }

    ull A[20];
    #pragma unroll
    for (int i = 0; i < 20; i++) A[i] = 0ull;

    const char* rp = smem + (size_t)lane * (QSTRIDE * 8);

    #pragma unroll
    for (int k = 0; k < 8; k++) {
        const int s  = k % NSTAGE;
        const int ph = (k / NSTAGE) & 1;

        mbar_wait(FULL + s * 8, ph);

        const char* zb = smem + STAGE_OFF + s * STAGE_BYTES;
        float4 c0 = *(const float4*)(zb +        (2 * w)     * 512 + lane * 16);
        float4 c1 = *(const float4*)(zb +        (2 * w + 1) * 512 + lane * 16);
        float4 c2 = *(const float4*)(zb + 8192 + (2 * w)     * 512 + lane * 16);
        float4 c3 = *(const float4*)(zb + 8192 + (2 * w + 1) * 512 + lane * 16);

        // duplicate z scalars into f32x2 operands (z is now latched in regs)
        ull d0[4], d1[4], d2[4], d3[4];
        d0[0] = pack2(c0.x, c0.x); d0[1] = pack2(c0.y, c0.y);
        d0[2] = pack2(c0.z, c0.z); d0[3] = pack2(c0.w, c0.w);
        d1[0] = pack2(c1.x, c1.x); d1[1] = pack2(c1.y, c1.y);
        d1[2] = pack2(c1.z, c1.z); d1[3] = pack2(c1.w, c1.w);
        d2[0] = pack2(c2.x, c2.x); d2[1] = pack2(c2.y, c2.y);
        d2[2] = pack2(c2.z, c2.z); d2[3] = pack2(c2.w, c2.w);
        d3[0] = pack2(c3.x, c3.x); d3[1] = pack2(c3.y, c3.y);
        d3[2] = pack2(c3.z, c3.z); d3[3] = pack2(c3.w, c3.w);

        // this warp is done with stage s
        if (lane == 0) mbar_arrive(EMPTY + s * 8);

        const char* rk = rp + k * (32 * QSTRIDE * 8);
        #pragma unroll
        for (int p = 0; p < 5; p++) {
            ulonglong2 fa = *(const ulonglong2*)(rk + p * 32);
            ulonglong2 fb = *(const ulonglong2*)(rk + p * 32 + 16);
            fma2(A[p * 4 + 0], d0[0], fa.x); fma2(A[p * 4 + 0], d0[1], fa.y);
            fma2(A[p * 4 + 0], d0[2], fb.x); fma2(A[p * 4 + 0], d0[3], fb.y);
            fma2(A[p * 4 + 1], d2[0], fa.x); fma2(A[p * 4 + 1], d2[1], fa.y);
            fma2(A[p * 4 + 1], d2[2], fb.x); fma2(A[p * 4 + 1], d2[3], fb.y);
            fma2(A[p * 4 + 2], d1[0], fa.x); fma2(A[p * 4 + 2], d1[1], fa.y);
            fma2(A[p * 4 + 2], d1[2], fb.x); fma2(A[p * 4 + 2], d1[3], fb.y);
            fma2(A[p * 4 + 3], d3[0], fa.x); fma2(A[p * 4 + 3], d3[1], fa.y);
            fma2(A[p * 4 + 3], d3[2], fb.x); fma2(A[p * 4 + 3], d3[3], fb.y);
        }

        // warp 0: refill stage s for iteration k+NSTAGE once all warps consumed it
        if (k + NSTAGE < 8 && tid < 32) {
            mbar_wait(EMPTY + s * 8, ph);
            if (lane == 0) mbar_expect_tx(FULL + s * 8, STAGE_BYTES);
            __syncwarp();
            bulk_cp(sbase + STAGE_OFF + s * STAGE_BYTES + parr * 8192 + prow * 512,
                    pbase + (k + NSTAGE) * 128, 512, FULL + s * 8);
        }
    }

    __syncthreads();   // all warps done with staged ref -> overlay reduction buffer

    // lane partials: 8 warps x 20 ull rows, stride 33 (conflict-free STS.64)
    ull* red = (ull*)smem;
    #pragma unroll
    for (int i = 0; i < 20; i++)
        red[(w * 20 + i) * 33 + lane] = A[i];
    __syncthreads();

    // 80 tasks: (warp w2, class-pair p, row j) -> 2 outputs each
    if (tid < 80) {
        const int w2 = tid / 10;
        const int q  = tid % 10;
        const int p  = q >> 1;
        const int j  = q & 1;
        const int mRe = w2 * 20 + p * 4 + j * 2;
        ull sre = 0ull, sim = 0ull;
        #pragma unroll
        for (int x = 0; x < 32; x++) {
            add2(sre, red[mRe * 33 + x]);
            add2(sim, red[(mRe + 1) * 33 + x]);
        }
        float reL, reH, imL, imH;
        unpack2(sre, reL, reH);
        unpack2(sim, imL, imH);
        const size_t row = (size_t)rowBase0 + (size_t)w2 * 2 + (size_t)j;
        out[row * NCLS + 2 * p]     = reL * reL + imL * imL;
        out[row * NCLS + 2 * p + 1] = reH * reH + imH * imH;
    }
}

extern "C" void kernel_launch(void* const* d_in, const int* in_sizes, int n_in,
                              void* d_out, int out_size) {
    const float* zre   = (const float*)d_in[0];
    const float* zim   = (const float*)d_in[1];
    const float* canon = (const float*)d_in[2];
    float* out = (float*)d_out;

    cudaFuncSetAttribute(swap_test_kernel,
                         cudaFuncAttributeMaxDynamicSharedMemorySize, SMEM_TOTAL);

    ref_pack_kernel<<<NCLS / 2, 256>>>(canon);
    swap_test_kernel<<<NROWS / 16, 256, SMEM_TOTAL>>>(zre, zim, out);
}

// round 9
// speedup vs baseline: 2.1494x; 2.1494x over previous
#include <cuda_runtime.h>

typedef unsigned long long ull;
typedef unsigned int u32;

#define NROWS   16384
#define DIMP    1024
#define NCLS    10
#define IMG     784
#define QSTRIDE 22                    // ull per d-quad group: 20 data + 2 pad (176 B)

#define REF_BYTES   45056             // 256 groups * 176 B
#define NSTAGE      3
#define WSTAGE      2048              // per-warp stage: 2 rows * 2 arrays * 512 B
#define Z_OFF       REF_BYTES
#define SMEM_TOTAL  (Z_OFF + 8 * NSTAGE * WSTAGE)   // 45056 + 49152 = 94208

// Packed reference pairs (prologue output), dense layout:
// g_refp[(d>>2)*20 + p*4 + (d&3)] = ( ref[2p][d], ref[2p+1][d] )
__device__ ull g_refp[256 * 20];

// ---------- f32x2 helpers ----------
__device__ __forceinline__ ull pack2(float lo, float hi) {
    ull r;
    asm("mov.b64 %0, {%1, %2};" : "=l"(r) : "f"(lo), "f"(hi));
    return r;
}
__device__ __forceinline__ void unpack2(ull v, float& lo, float& hi) {
    asm("mov.b64 {%0, %1}, %2;" : "=f"(lo), "=f"(hi) : "l"(v));
}
__device__ __forceinline__ void fma2(ull& acc, ull a, ull b) {
    asm("fma.rn.f32x2 %0, %1, %2, %0;" : "+l"(acc) : "l"(a), "l"(b));
}
__device__ __forceinline__ void add2(ull& acc, ull a) {
    asm("add.rn.f32x2 %0, %1, %0;" : "+l"(acc) : "l"(a));
}

// ---------- cp.async helpers (per-warp private pipeline, no barriers) ----------
__device__ __forceinline__ u32 smem_u32(const void* p) {
    u32 a;
    asm("{ .reg .u64 t; cvta.to.shared.u64 t, %1; cvt.u32.u64 %0, t; }" : "=r"(a) : "l"(p));
    return a;
}
__device__ __forceinline__ void cp16(u32 dst, const void* src) {
    asm volatile("cp.async.cg.shared.global [%0], [%1], 16;" :: "r"(dst), "l"(src) : "memory");
}
__device__ __forceinline__ void cp_commit() {
    asm volatile("cp.async.commit_group;" ::: "memory");
}
__device__ __forceinline__ void cp_wait2() {
    asm volatile("cp.async.wait_group 2;" ::: "memory");
}

// ---------- prologue: block p normalizes classes 2p, 2p+1, writes packed pairs ----------
__global__ void ref_pack_kernel(const float* __restrict__ canon) {
    __shared__ float v0[DIMP], v1[DIMP];
    __shared__ float wred[16];
    __shared__ float invs[2];
    const int p = blockIdx.x, t = threadIdx.x;
    const float* c0 = canon + (2 * p) * IMG;
    const float* c1 = canon + (2 * p + 1) * IMG;
    float s0 = 0.f, s1 = 0.f;
    for (int i = t; i < DIMP; i += 256) {
        float a = (i < IMG) ? c0[i] : 0.f;
        float b = (i < IMG) ? c1[i] : 0.f;
        v0[i] = a; v1[i] = b;
        s0 += a * a; s1 += b * b;
    }
    #pragma unroll
    for (int o = 16; o; o >>= 1) {
        s0 += __shfl_xor_sync(0xFFFFFFFFu, s0, o);
        s1 += __shfl_xor_sync(0xFFFFFFFFu, s1, o);
    }
    if ((t & 31) == 0) { wred[t >> 5] = s0; wred[8 + (t >> 5)] = s1; }
    __syncthreads();
    if (t == 0) {
        float a = 0.f, b = 0.f;
        #pragma unroll
        for (int i = 0; i < 8; i++) { a += wred[i]; b += wred[8 + i]; }
        invs[0] = 1.0f / sqrtf(a);
        invs[1] = 1.0f / sqrtf(b);
    }
    __syncthreads();
    const float i0 = invs[0], i1 = invs[1];
    for (int d = t; d < DIMP; d += 256)
        g_refp[(d >> 2) * 20 + p * 4 + (d & 3)] = pack2(v0[d] * i0, v1[d] * i1);
}

// ---------- main kernel ----------
// 256 threads = 8 warps, 2 rows/warp -> 16 rows/block, grid = 1024.
// Each warp owns a private 3-stage smem ring for its z tiles, filled with
// cp.async at prefetch distance 2. Same-warp cp.async -> wait -> LDS ordering
// means ZERO cross-warp synchronization in the main loop.
__global__ __launch_bounds__(256, 2) void swap_test_kernel(
    const float* __restrict__ zre, const float* __restrict__ zim,
    float* __restrict__ out) {

    extern __shared__ __align__(16) char smem[];
    const u32 sbase = smem_u32(smem);
    const int tid  = threadIdx.x;
    const int lane = tid & 31;
    const int w    = tid >> 5;
    const int rowBase0 = blockIdx.x * 16;

    // stage packed ref into smem (176 B groups: 20 data ull + 2 pad)
    {
        ull* s = (ull*)smem;
        for (int i = tid; i < 5120; i += 256) {
            const int q = i / 20;
            const int r = i - q * 20;
            s[q * QSTRIDE + r] = g_refp[i];
        }
    }

    // per-warp z sources (2 rows x {re,im})
    const float* zr0 = zre + (size_t)(rowBase0 + 2 * w)     * DIMP;
    const float* zr1 = zre + (size_t)(rowBase0 + 2 * w + 1) * DIMP;
    const float* zi0 = zim + (size_t)(rowBase0 + 2 * w)     * DIMP;
    const float* zi1 = zim + (size_t)(rowBase0 + 2 * w + 1) * DIMP;
    const u32 zring = sbase + Z_OFF + (u32)w * (NSTAGE * WSTAGE) + (u32)lane * 16;
    const int lo4 = lane * 4;

    // prime stages 0,1 (tiles 0,1)
    #pragma unroll
    for (int kk = 0; kk < 2; kk++) {
        const u32 d = zring + kk * WSTAGE;
        cp16(d,        zr0 + kk * 128 + lo4);
        cp16(d + 512,  zr1 + kk * 128 + lo4);
        cp16(d + 1024, zi0 + kk * 128 + lo4);
        cp16(d + 1536, zi1 + kk * 128 + lo4);
        cp_commit();
    }

    __syncthreads();   // ref staging visible to all warps

    ull A[20];
    #pragma unroll
    for (int i = 0; i < 20; i++) A[i] = 0ull;

    const char* rp = smem + (size_t)lane * (QSTRIDE * 8);

    #pragma unroll
    for (int k = 0; k < 8; k++) {
        // issue tile k+2 into stage (k+2)%3 (distance-2 prefetch)
        if (k < 6) {
            const int kk = k + 2;
            const u32 d = zring + (kk % NSTAGE) * WSTAGE;
            cp16(d,        zr0 + kk * 128 + lo4);
            cp16(d + 512,  zr1 + kk * 128 + lo4);
            cp16(d + 1024, zi0 + kk * 128 + lo4);
            cp16(d + 1536, zi1 + kk * 128 + lo4);
        }
        cp_commit();       // always commit (possibly empty) to keep count invariant
        cp_wait2();        // tile k's group is now complete

        const char* zb = smem + Z_OFF + (size_t)w * (NSTAGE * WSTAGE)
                              + (size_t)(k % NSTAGE) * WSTAGE + (size_t)lane * 16;
        float4 c0 = *(const float4*)(zb);
        float4 c1 = *(const float4*)(zb + 512);
        float4 c2 = *(const float4*)(zb + 1024);
        float4 c3 = *(const float4*)(zb + 1536);

        // duplicate z scalars into f32x2 operands (reused across 5 class-pairs)
        ull d0[4], d1[4], d2[4], d3[4];
        d0[0] = pack2(c0.x, c0.x); d0[1] = pack2(c0.y, c0.y);
        d0[2] = pack2(c0.z, c0.z); d0[3] = pack2(c0.w, c0.w);
        d1[0] = pack2(c1.x, c1.x); d1[1] = pack2(c1.y, c1.y);
        d1[2] = pack2(c1.z, c1.z); d1[3] = pack2(c1.w, c1.w);
        d2[0] = pack2(c2.x, c2.x); d2[1] = pack2(c2.y, c2.y);
        d2[2] = pack2(c2.z, c2.z); d2[3] = pack2(c2.w, c2.w);
        d3[0] = pack2(c3.x, c3.x); d3[1] = pack2(c3.y, c3.y);
        d3[2] = pack2(c3.z, c3.z); d3[3] = pack2(c3.w, c3.w);

        const char* rk = rp + k * (32 * QSTRIDE * 8);
        #pragma unroll
        for (int p = 0; p < 5; p++) {
            ulonglong2 fa = *(const ulonglong2*)(rk + p * 32);
            ulonglong2 fb = *(const ulonglong2*)(rk + p * 32 + 16);
            fma2(A[p * 4 + 0], d0[0], fa.x); fma2(A[p * 4 + 0], d0[1], fa.y);
            fma2(A[p * 4 + 0], d0[2], fb.x); fma2(A[p * 4 + 0], d0[3], fb.y);
            fma2(A[p * 4 + 1], d2[0], fa.x); fma2(A[p * 4 + 1], d2[1], fa.y);
            fma2(A[p * 4 + 1], d2[2], fb.x); fma2(A[p * 4 + 1], d2[3], fb.y);
            fma2(A[p * 4 + 2], d1[0], fa.x); fma2(A[p * 4 + 2], d1[1], fa.y);
            fma2(A[p * 4 + 2], d1[2], fb.x); fma2(A[p * 4 + 2], d1[3], fb.y);
            fma2(A[p * 4 + 3], d3[0], fa.x); fma2(A[p * 4 + 3], d3[1], fa.y);
            fma2(A[p * 4 + 3], d3[2], fb.x); fma2(A[p * 4 + 3], d3[3], fb.y);
        }
    }

    __syncthreads();   // all warps done with staged ref -> overlay reduction buffer

    // lane partials: 8 warps x 20 ull rows, stride 33 (conflict-free STS.64)
    ull* red = (ull*)smem;
    #pragma unroll
    for (int i = 0; i < 20; i++)
        red[(w * 20 + i) * 33 + lane] = A[i];
    __syncthreads();

    // 80 tasks: (warp w2, class-pair p, row j) -> 2 outputs each
    if (tid < 80) {
        const int w2 = tid / 10;
        const int q  = tid % 10;
        const int p  = q >> 1;
        const int j  = q & 1;
        const int mRe = w2 * 20 + p * 4 + j * 2;
        ull sre = 0ull, sim = 0ull;
        #pragma unroll
        for (int x = 0; x < 32; x++) {
            add2(sre, red[mRe * 33 + x]);
            add2(sim, red[(mRe + 1) * 33 + x]);
        }
        float reL, reH, imL, imH;
        unpack2(sre, reL, reH);
        unpack2(sim, imL, imH);
        const size_t row = (size_t)rowBase0 + (size_t)w2 * 2 + (size_t)j;
        out[row * NCLS + 2 * p]     = reL * reL + imL * imL;
        out[row * NCLS + 2 * p + 1] = reH * reH + imH * imH;
    }
}

extern "C" void kernel_launch(void* const* d_in, const int* in_sizes, int n_in,
                              void* d_out, int out_size) {
    const float* zre   = (const float*)d_in[0];
    const float* zim   = (const float*)d_in[1];
    const float* canon = (const float*)d_in[2];
    float* out = (float*)d_out;

    cudaFuncSetAttribute(swap_test_kernel,
                         cudaFuncAttributeMaxDynamicSharedMemorySize, SMEM_TOTAL);

    ref_pack_kernel<<<NCLS / 2, 256>>>(canon);
    swap_test_kernel<<<NROWS / 16, 256, SMEM_TOTAL>>>(zre, zim, out);
}